// round 15
// baseline (speedup 1.0000x reference)
#include <cuda_runtime.h>
#include <cuda_fp16.h>
#include <cstdint>

// Problem constants
#define N_   32
#define C_   64
#define T_   300
#define V_   25
#define O_   128
#define TO_  150
#define TV_  7500
#define TOV_ 3750
#define KT_  9

// Phase-split transposed agg layout: [n][v][row][c], row<224: even phase
// (t_in = 2*(row-2)), row>=224: odd phase (t_in = 2*(row-224-2)+1).
#define ROWS_ 448

__device__ float g_xtcn[N_ * O_ * TO_ * V_];         // 61.4 MB fp32
__device__ float g_beff[O_ * TO_];
__device__ __align__(16) unsigned short g_aggB[(size_t)N_ * V_ * ROWS_ * 64];  // fp16
__device__ __align__(16) unsigned short g_WtapH[9 * 128 * 64];  // fp16 (single term)
__device__ __align__(16) unsigned short g_WresH[128 * 64];      // res_w hi
__device__ __align__(16) unsigned short g_WresL[128 * 64];      // res_w lo
__device__ double g_sum[O_];
__device__ double g_sum2[O_];
__device__ float g_scale[O_];
__device__ float g_shift[O_];

// ---------------- PTX helpers ------------------------------------------------
__device__ __forceinline__ uint32_t smem_u32(const void* p) {
    uint32_t a;
    asm("{ .reg .u64 t; cvta.to.shared.u64 t, %1; cvt.u32.u64 %0, t; }" : "=r"(a) : "l"(p));
    return a;
}
__device__ __forceinline__ void ldsm_x4(uint32_t* r, uint32_t addr) {
    asm volatile("ldmatrix.sync.aligned.m8n8.x4.shared.b16 {%0,%1,%2,%3}, [%4];"
                 : "=r"(r[0]), "=r"(r[1]), "=r"(r[2]), "=r"(r[3]) : "r"(addr));
}
__device__ __forceinline__ void mma_f16(float* d, const uint32_t* a, const uint32_t* b) {
    asm volatile(
        "mma.sync.aligned.m16n8k16.row.col.f32.f16.f16.f32 "
        "{%0,%1,%2,%3}, {%4,%5,%6,%7}, {%8,%9}, {%0,%1,%2,%3};"
        : "+f"(d[0]), "+f"(d[1]), "+f"(d[2]), "+f"(d[3])
        : "r"(a[0]), "r"(a[1]), "r"(a[2]), "r"(a[3]), "r"(b[0]), "r"(b[1]));
}
__device__ __forceinline__ void cp_async16(uint32_t dst, const void* src) {
    asm volatile("cp.async.cg.shared.global [%0], [%1], 16;" :: "r"(dst), "l"(src));
}
#define CP_COMMIT() asm volatile("cp.async.commit_group;" ::: "memory")
#define CP_WAIT0()  asm volatile("cp.async.wait_group 0;" ::: "memory")
#define SWZ128(x) ((x) ^ (((x) >> 3) & 0x70))

// ---------------------------------------------------------------------------
// L1: k_wprep — fused gcn*tcn weight -> swizzled fp16 per-tap images.
// ---------------------------------------------------------------------------
__global__ void __launch_bounds__(128) k_wprep(const float* __restrict__ tcn_w,
                                               const float* __restrict__ gcn_w) {
    __shared__ float gc[O_];
    int ck = blockIdx.x;
    int c = ck / KT_, k = ck % KT_;
    int o = threadIdx.x;
    gc[o] = gcn_w[o * C_ + c];
    __syncthreads();
    const float* wrow = tcn_w + (size_t)o * O_ * KT_ + k;
    float s = 0.f;
    #pragma unroll 8
    for (int o2 = 0; o2 < O_; o2++) s += wrow[o2 * KT_] * gc[o2];
    __half h = __float2half_rn(s);
    uint32_t boff = SWZ128((uint32_t)(o * 128 + c * 2));
    g_WtapH[k * 8192 + (boff >> 1)] = *reinterpret_cast<unsigned short*>(&h);
}

// ---------------------------------------------------------------------------
// L2: k_beff — bias_eff + zero stats accumulators + res_w hi/lo images
// ---------------------------------------------------------------------------
__global__ void __launch_bounds__(128) k_beff(const float* __restrict__ tcn_w,
                                              const float* __restrict__ gcn_b,
                                              const float* __restrict__ tcn_b,
                                              const float* __restrict__ res_w) {
    __shared__ float red[128];
    __shared__ float Bk[KT_];
    int o = blockIdx.x, o2 = threadIdx.x;
    if (o2 == 0) { g_sum[o] = 0.0; g_sum2[o] = 0.0; }
    if (o2 < 64) {
        float w = res_w[o * C_ + o2];
        __half h = __float2half_rn(w);
        __half l = __float2half_rn(w - __half2float(h));
        uint32_t boff = SWZ128((uint32_t)(o * 128 + o2 * 2));
        g_WresH[boff >> 1] = *reinterpret_cast<unsigned short*>(&h);
        g_WresL[boff >> 1] = *reinterpret_cast<unsigned short*>(&l);
    }
    float gb = gcn_b[o2];
    const float* wrow = tcn_w + ((size_t)o * O_ + o2) * KT_;
    #pragma unroll
    for (int k = 0; k < KT_; k++) {
        red[o2] = wrow[k] * gb;
        __syncthreads();
        for (int st = 64; st > 0; st >>= 1) {
            if (o2 < st) red[o2] += red[o2 + st];
            __syncthreads();
        }
        if (o2 == 0) Bk[k] = red[0];
        __syncthreads();
    }
    float tb = tcn_b[o];
    for (int t = threadIdx.x; t < TO_; t += 128) {
        float s = tb;
        #pragma unroll
        for (int k = 0; k < KT_; k++) {
            int tp = 2 * t + k - 4;
            if (tp >= 0 && tp < T_) s += Bk[k];
        }
        g_beff[o * TO_ + t] = s;
    }
}

// ---------------------------------------------------------------------------
// L3: k_aggp — agg in phase-split transposed fp16 layout
// ---------------------------------------------------------------------------
__global__ void __launch_bounds__(256) k_aggp(const float* __restrict__ x,
                                              const float* __restrict__ A_parts,
                                              const float* __restrict__ ei) {
    __shared__ float sx[1600];
    __shared__ float As[625];
    __shared__ __align__(16) unsigned short souts[1600];
    int row = blockIdx.x, n = blockIdx.y, tid = threadIdx.x;
    int phase = (row >= 224) ? 1 : 0;
    int e = phase ? (row - 224) : row;
    int t_in = 2 * (e - 2) + phase;
    bool valid = (t_in >= 0) && (t_in < T_);

    if (valid) {
        float e0 = ei[0], e1 = ei[1], e2 = ei[2];
        for (int i = tid; i < 625; i += 256)
            As[i] = A_parts[i] * e0 + A_parts[625 + i] * e1 + A_parts[1250 + i] * e2;
        const float* xb = x + ((size_t)n * C_) * TV_ + t_in * V_;
        for (int i = tid; i < 1600; i += 256) {
            int c = i / 25, w = i - c * 25;
            sx[i] = xb[c * TV_ + w];
        }
        __syncthreads();
        for (int i = tid; i < 1600; i += 256) {
            int v = i >> 6, c = i & 63;
            float s = 0.f;
            #pragma unroll
            for (int w = 0; w < 25; w++) s += sx[c * 25 + w] * As[w * 25 + v];
            __half h = __float2half_rn(s);
            souts[v * 64 + c] = *reinterpret_cast<unsigned short*>(&h);
        }
        __syncthreads();
        int r7 = row & 7;
        for (int j = tid; j < 200; j += 256) {
            int v = j >> 3, q = j & 7;
            uint4 val = *(const uint4*)&souts[v * 64 + ((q ^ r7) << 3)];
            *((uint4*)(g_aggB + (((size_t)(n * 25 + v) * ROWS_ + row) << 6)) + q) = val;
        }
    } else {
        for (int j = tid; j < 200; j += 256) {
            int v = j >> 3, q = j & 7;
            *((uint4*)(g_aggB + (((size_t)(n * 25 + v) * ROWS_ + row) << 6)) + q) =
                make_uint4(0, 0, 0, 0);
        }
    }
}

// ---------------------------------------------------------------------------
// L4 (profiled slot): k_tcn_mma — SYNC-FREE tap-shift HMMA.
// 512 threads, 1 CTA/SM, 4 v per CTA (N=256).
// smem: B [8 sec x 72 rows x 128B] = 72KB | A all 9 taps = 144KB  -> 216KB
// One cp.async prologue + one barrier; the 9-tap MMA loop has NO syncs.
// ---------------------------------------------------------------------------
#define R_SEC  72
#define SEC_B  (R_SEC * 128)          // 9216
#define TB_OFF 0
#define TA_OFF (8 * SEC_B)            // 73728
#define SMEM_TOT (TA_OFF + 9 * 16384) // 221184

__global__ void __launch_bounds__(512, 1) k_tcn_mma() {
    extern __shared__ __align__(16) unsigned char smem[];
    int tid = threadIdx.x, lane = tid & 31, wid = tid >> 5;
    int wm = wid >> 3;                 // 0..1
    int wn = wid & 7;                  // 0..7
    int t0 = blockIdx.x * 64;
    int v0 = blockIdx.y * 4;
    int n = blockIdx.z;
    uint32_t sbase = smem_u32(smem);

    // ---- B: 8 sections (vsec 0..3, phase 0..1) x 72 rows (cp.async / zero)
    for (int j = tid; j < 4608; j += 512) {
        int sec = j / 576;
        int rq = j - sec * 576;
        int row = rq >> 3, q = rq & 7;
        int vsec = sec >> 1, phase = sec & 1;
        int vv = v0 + vsec;
        uint32_t dst = sbase + TB_OFF + sec * SEC_B + row * 128 + q * 16;
        if (row < 68 && vv < V_) {
            int grow = (phase ? 224 : 0) + t0 + row;
            cp_async16(dst, (const void*)(g_aggB +
                       (((size_t)(n * V_ + vv) * ROWS_ + grow) << 6) + q * 8));
        } else {
            *((uint4*)(smem + TB_OFF + sec * SEC_B + row * 128) + q) =
                make_uint4(0, 0, 0, 0);
        }
    }
    // ---- A: all 9 taps (144KB = 9216 x 16B)
    for (int j = tid; j < 9216; j += 512)
        cp_async16(sbase + TA_OFF + j * 16, (const void*)(g_WtapH + j * 8));
    CP_COMMIT();
    CP_WAIT0();
    __syncthreads();                   // the ONLY barrier before the epilogue

    // fragment addressing
    int la_row = ((lane >> 3) & 1) * 8 + (lane & 7);
    uint32_t xorA = (uint32_t)((lane & 7) << 4);
    uint32_t la_col = ((lane >> 4) & 1) * 16;
    uint32_t aRow = (uint32_t)(wm * 64 + la_row) * 128;
    int vsec_w = wn >> 1, trow = (wn & 1) * 32;
    uint32_t lb_col = (uint32_t)(((lane >> 3) & 1) * 16);
    uint32_t lrow8 = (uint32_t)(((lane >> 4) & 1) * 8 + (lane & 7));

    float acc[4][4][4] = {};

    for (int k = 0; k < 9; k++) {
        uint32_t abase = sbase + TA_OFF + (uint32_t)k * 16384;
        int phase = k & 1, jt = k >> 1;
        uint32_t secoff = (uint32_t)(vsec_w * 2 + phase) * SEC_B;
        uint32_t xorB = (uint32_t)(((jt + (lane & 7)) & 7) << 4);
        uint32_t rb4 = (uint32_t)(jt + trow) + lrow8;

        #pragma unroll
        for (int ks = 0; ks < 4; ks++) {
            uint32_t cb = ((uint32_t)(ks * 32) + lb_col) ^ xorB;
            uint32_t bh[4][2];
            {
                uint32_t a0 = sbase + TB_OFF + secoff + rb4 * 128 + cb;
                ldsm_x4(&bh[0][0], a0);
                ldsm_x4(&bh[2][0], a0 + 16 * 128);
            }
            uint32_t ca = ((uint32_t)(ks * 32) + la_col) ^ xorA;
            #pragma unroll
            for (int mt = 0; mt < 4; mt++) {
                uint32_t ah[4];
                ldsm_x4(ah, abase + aRow + mt * 2048 + ca);
                #pragma unroll
                for (int nt = 0; nt < 4; nt++)
                    mma_f16(acc[mt][nt], ah, bh[nt]);
            }
        }
    }

    // ---- epilogue + fused stats
    __syncthreads();                   // safe to reuse smem
    float* ssum = (float*)smem;
    float* ssum2 = ssum + 128;
    if (tid < 128) { ssum[tid] = 0.f; ssum2[tid] = 0.f; }
    __syncthreads();

    float* Out = g_xtcn + (size_t)n * O_ * TOV_;
    int qr = lane >> 2, qc = (lane & 3) * 2;
    int vv = v0 + vsec_w;
    #pragma unroll
    for (int mt = 0; mt < 4; mt++) {
        #pragma unroll
        for (int hh = 0; hh < 2; hh++) {
            int o = wm * 64 + mt * 16 + qr + hh * 8;
            const float* be = g_beff + o * TO_;
            float* orow = Out + (size_t)o * TOV_;
            float s1 = 0.f, s2 = 0.f;
            #pragma unroll
            for (int nt = 0; nt < 4; nt++) {
                int t = t0 + trow + nt * 8 + qc;
                if (vv < V_) {
                    if (t < TO_) {
                        float y = acc[mt][nt][hh * 2 + 0] + be[t];
                        orow[t * V_ + vv] = y;
                        s1 += y; s2 += y * y;
                    }
                    if (t + 1 < TO_) {
                        float y = acc[mt][nt][hh * 2 + 1] + be[t + 1];
                        orow[(t + 1) * V_ + vv] = y;
                        s1 += y; s2 += y * y;
                    }
                }
            }
            s1 += __shfl_xor_sync(0xFFFFFFFFu, s1, 1);
            s1 += __shfl_xor_sync(0xFFFFFFFFu, s1, 2);
            s2 += __shfl_xor_sync(0xFFFFFFFFu, s2, 1);
            s2 += __shfl_xor_sync(0xFFFFFFFFu, s2, 2);
            if ((lane & 3) == 0) {
                atomicAdd(&ssum[o], s1);
                atomicAdd(&ssum2[o], s2);
            }
        }
    }
    __syncthreads();
    if (tid < 128) {
        atomicAdd(&g_sum[tid], (double)ssum[tid]);
        atomicAdd(&g_sum2[tid], (double)ssum2[tid]);
    }
}

// ---------------------------------------------------------------------------
// L5: k_statsfin — finalize BN scale/shift (res_b folded into shift)
// ---------------------------------------------------------------------------
__global__ void k_statsfin(const float* __restrict__ gamma,
                           const float* __restrict__ beta,
                           const float* __restrict__ res_b) {
    int o = threadIdx.x;
    double cnt = (double)N_ * (double)TOV_;
    double mean = g_sum[o] / cnt;
    double var = g_sum2[o] / cnt - mean * mean;
    float rstd = (float)(1.0 / sqrt(var + 1e-5));
    float sc = gamma[o] * rstd;
    g_scale[o] = sc;
    g_shift[o] = beta[o] - (float)mean * sc + res_b[o];
}

// ---------------------------------------------------------------------------
// L6: k_fin_mma — residual HMMA (K=64, res_w 2-term) + BN + add + ReLU.
// CTA = (contiguous s-block of 128, n). Coalesced epilogue.
// smem: B 16KB | A hi 16KB | A lo 16KB
// ---------------------------------------------------------------------------
#define FB_OFF 0
#define FAH    16384
#define FAL    32768
#define SMEM_FIN 49152

__global__ void __launch_bounds__(256, 2) k_fin_mma(const float* __restrict__ x,
                                                    float* __restrict__ out) {
    extern __shared__ __align__(16) unsigned char smem[];
    int tid = threadIdx.x, lane = tid & 31, wid = tid >> 5;
    int wm = wid >> 2, wn = wid & 3;
    int n = blockIdx.y;
    int s0 = blockIdx.x * 128;
    uint32_t sbase = smem_u32(smem);

    // A copy (res_w hi/lo images, 16KB each = 1024 uint4 each)
    #pragma unroll
    for (int i = 0; i < 8; i++) {
        int j = tid + 256 * i;                // 0..2047
        int p = j >> 10, idx = j & 1023;
        *((uint4*)(smem + (p ? FAL : FAH)) + idx) =
            *((const uint4*)(p ? g_WresL : g_WresH) + idx);
    }

    // B gather: thread covers s-row r, 32 c values (half selects c range)
    {
        int r = tid & 127, half = tid >> 7;
        int s = s0 + r;
        bool valid = s < TOV_;
        int t2 = valid ? (s / V_) * 2 : 0;
        int v = valid ? (s % V_) : 0;
        const float* xb = x + (size_t)n * C_ * TV_ + (size_t)t2 * V_ + v;
        int xors = (r & 7) << 4;
        #pragma unroll
        for (int j = 0; j < 16; j++) {
            int c0 = half * 32 + j * 2;
            float f0 = valid ? xb[(size_t)c0 * TV_] : 0.f;
            float f1 = valid ? xb[(size_t)(c0 + 1) * TV_] : 0.f;
            __half h0 = __float2half_rn(f0);
            __half h1 = __float2half_rn(f1);
            uint32_t pair = (uint32_t)*reinterpret_cast<unsigned short*>(&h0) |
                            ((uint32_t)*reinterpret_cast<unsigned short*>(&h1) << 16);
            uint32_t off = (uint32_t)(r * 128 + ((c0 * 2) ^ xors));
            *reinterpret_cast<uint32_t*>(smem + FB_OFF + off) = pair;
        }
    }
    __syncthreads();

    // fragment addressing
    int la_row = ((lane >> 3) & 1) * 8 + (lane & 7);
    uint32_t xorA = (uint32_t)((lane & 7) << 4);
    uint32_t la_col = ((lane >> 4) & 1) * 16;
    uint32_t aRow = (uint32_t)(wm * 64 + la_row) * 128;
    uint32_t lb_col = (uint32_t)(((lane >> 3) & 1) * 16);
    uint32_t lrow8 = (uint32_t)(((lane >> 4) & 1) * 8 + (lane & 7));
    uint32_t rb4 = (uint32_t)(wn * 32) + lrow8;
    uint32_t xorB = (uint32_t)((lane & 7) << 4);

    float acc[4][4][4] = {};

    #pragma unroll
    for (int ks = 0; ks < 4; ks++) {
        uint32_t cb = ((uint32_t)(ks * 32) + lb_col) ^ xorB;
        uint32_t bh[4][2];
        {
            uint32_t a0 = sbase + FB_OFF + rb4 * 128 + cb;
            ldsm_x4(&bh[0][0], a0);
            ldsm_x4(&bh[2][0], a0 + 16 * 128);
        }
        uint32_t ca = ((uint32_t)(ks * 32) + la_col) ^ xorA;
        #pragma unroll
        for (int mt = 0; mt < 4; mt++) {
            uint32_t ah[4], al[4];
            ldsm_x4(ah, sbase + FAH + aRow + mt * 2048 + ca);
            ldsm_x4(al, sbase + FAL + aRow + mt * 2048 + ca);
            #pragma unroll
            for (int nt = 0; nt < 4; nt++) {
                mma_f16(acc[mt][nt], ah, bh[nt]);
                mma_f16(acc[mt][nt], al, bh[nt]);
            }
        }
    }

    // epilogue: out = relu(xtcn*scale + shift + res)   (res_b in shift)
    const float* Tcn = g_xtcn + (size_t)n * O_ * TOV_;
    float* Out = out + (size_t)n * O_ * TOV_;
    int qr = lane >> 2, qc = (lane & 3) * 2;
    #pragma unroll
    for (int mt = 0; mt < 4; mt++) {
        #pragma unroll
        for (int hh = 0; hh < 2; hh++) {
            int o = wm * 64 + mt * 16 + qr + hh * 8;
            float sc = g_scale[o];
            float sh = g_shift[o];
            const float* trow = Tcn + (size_t)o * TOV_;
            float* orow = Out + (size_t)o * TOV_;
            #pragma unroll
            for (int nt = 0; nt < 4; nt++) {
                int s = s0 + wn * 32 + nt * 8 + qc;
                if (s < TOV_) {
                    float y = trow[s] * sc + sh + acc[mt][nt][hh * 2 + 0];
                    orow[s] = fmaxf(y, 0.f);
                }
                if (s + 1 < TOV_) {
                    float y = trow[s + 1] * sc + sh + acc[mt][nt][hh * 2 + 1];
                    orow[s + 1] = fmaxf(y, 0.f);
                }
            }
        }
    }
}

// ---------------------------------------------------------------------------
extern "C" void kernel_launch(void* const* d_in, const int* in_sizes, int n_in,
                              void* d_out, int out_size) {
    const float* x       = (const float*)d_in[0];
    const float* A_parts = (const float*)d_in[1];
    const float* ei      = (const float*)d_in[2];
    const float* gcn_w   = (const float*)d_in[3];
    const float* gcn_b   = (const float*)d_in[4];
    const float* tcn_w   = (const float*)d_in[5];
    const float* tcn_b   = (const float*)d_in[6];
    const float* bn_g    = (const float*)d_in[7];
    const float* bn_b    = (const float*)d_in[8];
    const float* res_w   = (const float*)d_in[9];
    const float* res_b   = (const float*)d_in[10];
    float* out = (float*)d_out;

    cudaFuncSetAttribute(k_tcn_mma, cudaFuncAttributeMaxDynamicSharedMemorySize,
                         SMEM_TOT);
    cudaFuncSetAttribute(k_fin_mma, cudaFuncAttributeMaxDynamicSharedMemorySize,
                         SMEM_FIN);

    k_wprep<<<576, 128>>>(tcn_w, gcn_w);                 // 1
    k_beff<<<O_, 128>>>(tcn_w, gcn_b, tcn_b, res_w);     // 2
    dim3 gagg(ROWS_, N_);
    k_aggp<<<gagg, 256>>>(x, A_parts, ei);               // 3
    dim3 gtcn(3, 7, N_);
    k_tcn_mma<<<gtcn, 512, SMEM_TOT>>>();                // 4  <- profiled
    k_statsfin<<<1, 128>>>(bn_g, bn_b, res_b);           // 5
    dim3 gfin((TOV_ + 127) / 128, N_);
    k_fin_mma<<<gfin, 256, SMEM_FIN>>>(x, out);          // 6
}

// round 16
// speedup vs baseline: 1.2097x; 1.2097x over previous
#include <cuda_runtime.h>
#include <cuda_fp16.h>
#include <cstdint>

// Problem constants
#define N_   32
#define C_   64
#define T_   300
#define V_   25
#define O_   128
#define TO_  150
#define TV_  7500
#define TOV_ 3750
#define KT_  9

// Phase-split transposed agg layout: [n][v][row][c], row<224: even phase
// (t_in = 2*(row-2)), row>=224: odd phase (t_in = 2*(row-224-2)+1).
#define ROWS_ 448

__device__ float g_xtcn[N_ * O_ * TO_ * V_];         // 61.4 MB fp32
__device__ float g_beff[O_ * TO_];
__device__ __align__(16) unsigned short g_aggB[(size_t)N_ * V_ * ROWS_ * 64];  // fp16
__device__ __align__(16) unsigned short g_WtapH[9 * 128 * 64];  // fp16 (single term)
__device__ __align__(16) unsigned short g_WresH[128 * 64];      // res_w hi
__device__ __align__(16) unsigned short g_WresL[128 * 64];      // res_w lo
__device__ double g_sum[O_];
__device__ double g_sum2[O_];
__device__ float g_scale[O_];
__device__ float g_shift[O_];

// ---------------- PTX helpers ------------------------------------------------
__device__ __forceinline__ uint32_t smem_u32(const void* p) {
    uint32_t a;
    asm("{ .reg .u64 t; cvta.to.shared.u64 t, %1; cvt.u32.u64 %0, t; }" : "=r"(a) : "l"(p));
    return a;
}
__device__ __forceinline__ void ldsm_x4(uint32_t* r, uint32_t addr) {
    asm volatile("ldmatrix.sync.aligned.m8n8.x4.shared.b16 {%0,%1,%2,%3}, [%4];"
                 : "=r"(r[0]), "=r"(r[1]), "=r"(r[2]), "=r"(r[3]) : "r"(addr));
}
__device__ __forceinline__ void mma_f16(float* d, const uint32_t* a, const uint32_t* b) {
    asm volatile(
        "mma.sync.aligned.m16n8k16.row.col.f32.f16.f16.f32 "
        "{%0,%1,%2,%3}, {%4,%5,%6,%7}, {%8,%9}, {%0,%1,%2,%3};"
        : "+f"(d[0]), "+f"(d[1]), "+f"(d[2]), "+f"(d[3])
        : "r"(a[0]), "r"(a[1]), "r"(a[2]), "r"(a[3]), "r"(b[0]), "r"(b[1]));
}
__device__ __forceinline__ void cp_async16(uint32_t dst, const void* src) {
    asm volatile("cp.async.cg.shared.global [%0], [%1], 16;" :: "r"(dst), "l"(src));
}
#define CP_COMMIT() asm volatile("cp.async.commit_group;" ::: "memory")
#define CP_WAIT0()  asm volatile("cp.async.wait_group 0;" ::: "memory")
#define SWZ128(x) ((x) ^ (((x) >> 3) & 0x70))

// ---------------------------------------------------------------------------
// L1: k_wprep — fused gcn*tcn weight -> swizzled fp16 per-tap images.
// ---------------------------------------------------------------------------
__global__ void __launch_bounds__(128) k_wprep(const float* __restrict__ tcn_w,
                                               const float* __restrict__ gcn_w) {
    __shared__ float gc[O_];
    int ck = blockIdx.x;
    int c = ck / KT_, k = ck % KT_;
    int o = threadIdx.x;
    gc[o] = gcn_w[o * C_ + c];
    __syncthreads();
    const float* wrow = tcn_w + (size_t)o * O_ * KT_ + k;
    float s = 0.f;
    #pragma unroll 8
    for (int o2 = 0; o2 < O_; o2++) s += wrow[o2 * KT_] * gc[o2];
    __half h = __float2half_rn(s);
    uint32_t boff = SWZ128((uint32_t)(o * 128 + c * 2));
    g_WtapH[k * 8192 + (boff >> 1)] = *reinterpret_cast<unsigned short*>(&h);
}

// ---------------------------------------------------------------------------
// L2: k_beff — bias_eff + zero stats accumulators + res_w hi/lo images
// ---------------------------------------------------------------------------
__global__ void __launch_bounds__(128) k_beff(const float* __restrict__ tcn_w,
                                              const float* __restrict__ gcn_b,
                                              const float* __restrict__ tcn_b,
                                              const float* __restrict__ res_w) {
    __shared__ float red[128];
    __shared__ float Bk[KT_];
    int o = blockIdx.x, o2 = threadIdx.x;
    if (o2 == 0) { g_sum[o] = 0.0; g_sum2[o] = 0.0; }
    if (o2 < 64) {
        float w = res_w[o * C_ + o2];
        __half h = __float2half_rn(w);
        __half l = __float2half_rn(w - __half2float(h));
        uint32_t boff = SWZ128((uint32_t)(o * 128 + o2 * 2));
        g_WresH[boff >> 1] = *reinterpret_cast<unsigned short*>(&h);
        g_WresL[boff >> 1] = *reinterpret_cast<unsigned short*>(&l);
    }
    float gb = gcn_b[o2];
    const float* wrow = tcn_w + ((size_t)o * O_ + o2) * KT_;
    #pragma unroll
    for (int k = 0; k < KT_; k++) {
        red[o2] = wrow[k] * gb;
        __syncthreads();
        for (int st = 64; st > 0; st >>= 1) {
            if (o2 < st) red[o2] += red[o2 + st];
            __syncthreads();
        }
        if (o2 == 0) Bk[k] = red[0];
        __syncthreads();
    }
    float tb = tcn_b[o];
    for (int t = threadIdx.x; t < TO_; t += 128) {
        float s = tb;
        #pragma unroll
        for (int k = 0; k < KT_; k++) {
            int tp = 2 * t + k - 4;
            if (tp >= 0 && tp < T_) s += Bk[k];
        }
        g_beff[o * TO_ + t] = s;
    }
}

// ---------------------------------------------------------------------------
// L3: k_aggp — agg in phase-split transposed fp16 layout
// ---------------------------------------------------------------------------
__global__ void __launch_bounds__(256) k_aggp(const float* __restrict__ x,
                                              const float* __restrict__ A_parts,
                                              const float* __restrict__ ei) {
    __shared__ float sx[1600];
    __shared__ float As[625];
    __shared__ __align__(16) unsigned short souts[1600];
    int row = blockIdx.x, n = blockIdx.y, tid = threadIdx.x;
    int phase = (row >= 224) ? 1 : 0;
    int e = phase ? (row - 224) : row;
    int t_in = 2 * (e - 2) + phase;
    bool valid = (t_in >= 0) && (t_in < T_);

    if (valid) {
        float e0 = ei[0], e1 = ei[1], e2 = ei[2];
        for (int i = tid; i < 625; i += 256)
            As[i] = A_parts[i] * e0 + A_parts[625 + i] * e1 + A_parts[1250 + i] * e2;
        const float* xb = x + ((size_t)n * C_) * TV_ + t_in * V_;
        for (int i = tid; i < 1600; i += 256) {
            int c = i / 25, w = i - c * 25;
            sx[i] = xb[c * TV_ + w];
        }
        __syncthreads();
        for (int i = tid; i < 1600; i += 256) {
            int v = i >> 6, c = i & 63;
            float s = 0.f;
            #pragma unroll
            for (int w = 0; w < 25; w++) s += sx[c * 25 + w] * As[w * 25 + v];
            __half h = __float2half_rn(s);
            souts[v * 64 + c] = *reinterpret_cast<unsigned short*>(&h);
        }
        __syncthreads();
        int r7 = row & 7;
        for (int j = tid; j < 200; j += 256) {
            int v = j >> 3, q = j & 7;
            uint4 val = *(const uint4*)&souts[v * 64 + ((q ^ r7) << 3)];
            *((uint4*)(g_aggB + (((size_t)(n * 25 + v) * ROWS_ + row) << 6)) + q) = val;
        }
    } else {
        for (int j = tid; j < 200; j += 256) {
            int v = j >> 3, q = j & 7;
            *((uint4*)(g_aggB + (((size_t)(n * 25 + v) * ROWS_ + row) << 6)) + q) =
                make_uint4(0, 0, 0, 0);
        }
    }
}

// ---------------------------------------------------------------------------
// L4 (profiled slot): k_tcn_mma — tap-shift HMMA fp16 single-term,
// double-buffered A via cp.async, 4 consecutive v per CTA, STAGED epilogue.
// CTA tile: 128 o x (4 v x 32 t).  Warp: 64 o x (1 v x 32 t).
// smem: B [8 sec(vsec,phase) x 40 rows x 128B]=40KB | A buf0 16KB | A buf1 16KB
// Epilogue stages to smem (128 x 132 fp32) then copies out in 16B v-runs.
// ---------------------------------------------------------------------------
#define BROWS  40
#define BSEC   (BROWS * 128)          // 5120
#define TB_OFF 0
#define TA0    40960
#define TA1    57344
#define SMEM_TOT 73728

__global__ void __launch_bounds__(256, 2) k_tcn_mma() {
    extern __shared__ __align__(16) unsigned char smem[];
    int tid = threadIdx.x, lane = tid & 31, wid = tid >> 5;
    int wm = wid >> 2;                 // 0..1 (o half)
    int vsec_w = wid & 3;              // 0..3 (one v per warp)
    int t0 = blockIdx.x * 32;
    int v0 = blockIdx.y * 4;
    int n = blockIdx.z;
    uint32_t sbase = smem_u32(smem);

    // ---- B copy: 8 sections (vsec 0..3, phase 0..1) x 36 rows used
    for (int j = tid; j < 2304; j += 256) {
        int sec = j / 288;
        int rq = j - sec * 288;
        int row = rq >> 3, q = rq & 7;   // row 0..35
        int vsec = sec >> 1, phase = sec & 1;
        int vv = v0 + vsec;
        uint4 val = make_uint4(0, 0, 0, 0);
        if (vv < V_) {
            int grow = (phase ? 224 : 0) + t0 + row;   // <= 387 < 448
            val = *((const uint4*)(g_aggB +
                    (((size_t)(n * V_ + vv) * ROWS_ + grow) << 6)) + q);
        }
        *((uint4*)(smem + TB_OFF + sec * BSEC + row * 128) + q) = val;
    }

    // ---- prologue: A tap 0 -> buf0 via cp.async (16KB = 1024 x 16B)
    {
        #pragma unroll
        for (int i = 0; i < 4; i++) {
            int idx = tid + 256 * i;
            cp_async16(sbase + TA0 + idx * 16, (const void*)(g_WtapH + idx * 8));
        }
        CP_COMMIT();
    }

    // fragment addressing
    int la_row = ((lane >> 3) & 1) * 8 + (lane & 7);
    uint32_t xorA = (uint32_t)((lane & 7) << 4);
    uint32_t la_col = ((lane >> 4) & 1) * 16;
    uint32_t aRow = (uint32_t)(wm * 64 + la_row) * 128;
    uint32_t lb_col = (uint32_t)(((lane >> 3) & 1) * 16);
    uint32_t lrow8 = (uint32_t)(((lane >> 4) & 1) * 8 + (lane & 7));

    float acc[4][4][4] = {};

    CP_WAIT0();
    __syncthreads();

    for (int k = 0; k < 9; k++) {
        uint32_t abuf = (k & 1) ? TA1 : TA0;
        if (k < 8) {
            uint32_t nbuf = (k & 1) ? TA0 : TA1;
            const unsigned short* srcH = g_WtapH + (k + 1) * 8192;
            #pragma unroll
            for (int i = 0; i < 4; i++) {
                int idx = tid + 256 * i;
                cp_async16(sbase + nbuf + idx * 16, (const void*)(srcH + idx * 8));
            }
            CP_COMMIT();
        }

        int phase = k & 1, jt = k >> 1;
        uint32_t secoff = (uint32_t)(vsec_w * 2 + phase) * BSEC;
        uint32_t xorB = (uint32_t)(((jt + (lane & 7)) & 7) << 4);
        uint32_t rb4 = (uint32_t)jt + lrow8;       // rows jt..jt+35 max (<36+pad)

        #pragma unroll
        for (int ks = 0; ks < 4; ks++) {
            uint32_t cb = ((uint32_t)(ks * 32) + lb_col) ^ xorB;
            uint32_t bh[4][2];
            {
                uint32_t a0 = sbase + TB_OFF + secoff + rb4 * 128 + cb;
                ldsm_x4(&bh[0][0], a0);
                ldsm_x4(&bh[2][0], a0 + 16 * 128);
            }
            uint32_t ca = ((uint32_t)(ks * 32) + la_col) ^ xorA;
            #pragma unroll
            for (int mt = 0; mt < 4; mt++) {
                uint32_t ah[4];
                ldsm_x4(ah, abuf + sbase + aRow + mt * 2048 + ca);
                #pragma unroll
                for (int nt = 0; nt < 4; nt++)
                    mma_f16(acc[mt][nt], ah, bh[nt]);
            }
        }

        if (k < 8) CP_WAIT0();
        __syncthreads();
    }

    // ---- staged epilogue + fused stats (smem fully reusable now)
    float* stage = (float*)smem;                    // 128 x 132 (padded)
    float* ssum  = (float*)(smem + 128 * 132 * 4);  // 67584
    float* ssum2 = ssum + 128;                      // ends 68608 <= 73728
    if (tid < 128) { ssum[tid] = 0.f; ssum2[tid] = 0.f; }
    __syncthreads();

    int qr = lane >> 2, qc = (lane & 3) * 2;
    int vv = v0 + vsec_w;
    bool vok = vv < V_;
    #pragma unroll
    for (int mt = 0; mt < 4; mt++) {
        #pragma unroll
        for (int hh = 0; hh < 2; hh++) {
            int o = wm * 64 + mt * 16 + qr + hh * 8;
            const float* be = g_beff + o * TO_;
            float s1 = 0.f, s2 = 0.f;
            #pragma unroll
            for (int nt = 0; nt < 4; nt++) {
                int tloc = nt * 8 + qc;
                int t = t0 + tloc;
                float y0 = 0.f, y1 = 0.f;
                if (vok && t < TO_) {
                    y0 = acc[mt][nt][hh * 2 + 0] + be[t];
                    s1 += y0; s2 += y0 * y0;
                }
                if (vok && t + 1 < TO_) {
                    y1 = acc[mt][nt][hh * 2 + 1] + be[t + 1];
                    s1 += y1; s2 += y1 * y1;
                }
                stage[o * 132 + tloc * 4 + vsec_w] = y0;
                stage[o * 132 + (tloc + 1) * 4 + vsec_w] = y1;
            }
            s1 += __shfl_xor_sync(0xFFFFFFFFu, s1, 1);
            s1 += __shfl_xor_sync(0xFFFFFFFFu, s1, 2);
            s2 += __shfl_xor_sync(0xFFFFFFFFu, s2, 1);
            s2 += __shfl_xor_sync(0xFFFFFFFFu, s2, 2);
            if ((lane & 3) == 0) {
                atomicAdd(&ssum[o], s1);
                atomicAdd(&ssum2[o], s2);
            }
        }
    }
    __syncthreads();

    // copy-out: 16B v-runs (4 consecutive v per (o,t))
    float* Out = g_xtcn + (size_t)n * O_ * TOV_;
    for (int j = tid; j < 16384; j += 256) {
        int o = j >> 7, r = j & 127;
        int tl = r >> 2, v = r & 3;
        int t = t0 + tl, vv2 = v0 + v;
        if (t < TO_ && vv2 < V_)
            Out[(size_t)o * TOV_ + t * V_ + vv2] = stage[o * 132 + r];
    }
    if (tid < 128) {
        atomicAdd(&g_sum[tid], (double)ssum[tid]);
        atomicAdd(&g_sum2[tid], (double)ssum2[tid]);
    }
}

// ---------------------------------------------------------------------------
// L5: k_statsfin — finalize BN scale/shift (res_b folded into shift)
// ---------------------------------------------------------------------------
__global__ void k_statsfin(const float* __restrict__ gamma,
                           const float* __restrict__ beta,
                           const float* __restrict__ res_b) {
    int o = threadIdx.x;
    double cnt = (double)N_ * (double)TOV_;
    double mean = g_sum[o] / cnt;
    double var = g_sum2[o] / cnt - mean * mean;
    float rstd = (float)(1.0 / sqrt(var + 1e-5));
    float sc = gamma[o] * rstd;
    g_scale[o] = sc;
    g_shift[o] = beta[o] - (float)mean * sc + res_b[o];
}

// ---------------------------------------------------------------------------
// L6: k_fin_mma — residual HMMA (K=64, res_w 2-term) + BN + add + ReLU.
// CTA = (contiguous s-block of 128, n). Coalesced epilogue.
// smem: B 16KB | A hi 16KB | A lo 16KB
// ---------------------------------------------------------------------------
#define FB_OFF 0
#define FAH    16384
#define FAL    32768
#define SMEM_FIN 49152

__global__ void __launch_bounds__(256, 2) k_fin_mma(const float* __restrict__ x,
                                                    float* __restrict__ out) {
    extern __shared__ __align__(16) unsigned char smem[];
    int tid = threadIdx.x, lane = tid & 31, wid = tid >> 5;
    int wm = wid >> 2, wn = wid & 3;
    int n = blockIdx.y;
    int s0 = blockIdx.x * 128;
    uint32_t sbase = smem_u32(smem);

    // A copy (res_w hi/lo images, 16KB each = 1024 uint4 each)
    #pragma unroll
    for (int i = 0; i < 8; i++) {
        int j = tid + 256 * i;                // 0..2047
        int p = j >> 10, idx = j & 1023;
        *((uint4*)(smem + (p ? FAL : FAH)) + idx) =
            *((const uint4*)(p ? g_WresL : g_WresH) + idx);
    }

    // B gather: thread covers s-row r, 32 c values (half selects c range)
    {
        int r = tid & 127, half = tid >> 7;
        int s = s0 + r;
        bool valid = s < TOV_;
        int t2 = valid ? (s / V_) * 2 : 0;
        int v = valid ? (s % V_) : 0;
        const float* xb = x + (size_t)n * C_ * TV_ + (size_t)t2 * V_ + v;
        int xors = (r & 7) << 4;
        #pragma unroll
        for (int j = 0; j < 16; j++) {
            int c0 = half * 32 + j * 2;
            float f0 = valid ? xb[(size_t)c0 * TV_] : 0.f;
            float f1 = valid ? xb[(size_t)(c0 + 1) * TV_] : 0.f;
            __half h0 = __float2half_rn(f0);
            __half h1 = __float2half_rn(f1);
            uint32_t pair = (uint32_t)*reinterpret_cast<unsigned short*>(&h0) |
                            ((uint32_t)*reinterpret_cast<unsigned short*>(&h1) << 16);
            uint32_t off = (uint32_t)(r * 128 + ((c0 * 2) ^ xors));
            *reinterpret_cast<uint32_t*>(smem + FB_OFF + off) = pair;
        }
    }
    __syncthreads();

    // fragment addressing
    int la_row = ((lane >> 3) & 1) * 8 + (lane & 7);
    uint32_t xorA = (uint32_t)((lane & 7) << 4);
    uint32_t la_col = ((lane >> 4) & 1) * 16;
    uint32_t aRow = (uint32_t)(wm * 64 + la_row) * 128;
    uint32_t lb_col = (uint32_t)(((lane >> 3) & 1) * 16);
    uint32_t lrow8 = (uint32_t)(((lane >> 4) & 1) * 8 + (lane & 7));
    uint32_t rb4 = (uint32_t)(wn * 32) + lrow8;
    uint32_t xorB = (uint32_t)((lane & 7) << 4);

    float acc[4][4][4] = {};

    #pragma unroll
    for (int ks = 0; ks < 4; ks++) {
        uint32_t cb = ((uint32_t)(ks * 32) + lb_col) ^ xorB;
        uint32_t bh[4][2];
        {
            uint32_t a0 = sbase + FB_OFF + rb4 * 128 + cb;
            ldsm_x4(&bh[0][0], a0);
            ldsm_x4(&bh[2][0], a0 + 16 * 128);
        }
        uint32_t ca = ((uint32_t)(ks * 32) + la_col) ^ xorA;
        #pragma unroll
        for (int mt = 0; mt < 4; mt++) {
            uint32_t ah[4], al[4];
            ldsm_x4(ah, sbase + FAH + aRow + mt * 2048 + ca);
            ldsm_x4(al, sbase + FAL + aRow + mt * 2048 + ca);
            #pragma unroll
            for (int nt = 0; nt < 4; nt++) {
                mma_f16(acc[mt][nt], ah, bh[nt]);
                mma_f16(acc[mt][nt], al, bh[nt]);
            }
        }
    }

    // epilogue: out = relu(xtcn*scale + shift + res)   (res_b in shift)
    const float* Tcn = g_xtcn + (size_t)n * O_ * TOV_;
    float* Out = out + (size_t)n * O_ * TOV_;
    int qr = lane >> 2, qc = (lane & 3) * 2;
    #pragma unroll
    for (int mt = 0; mt < 4; mt++) {
        #pragma unroll
        for (int hh = 0; hh < 2; hh++) {
            int o = wm * 64 + mt * 16 + qr + hh * 8;
            float sc = g_scale[o];
            float sh = g_shift[o];
            const float* trow = Tcn + (size_t)o * TOV_;
            float* orow = Out + (size_t)o * TOV_;
            #pragma unroll
            for (int nt = 0; nt < 4; nt++) {
                int s = s0 + wn * 32 + nt * 8 + qc;
                if (s < TOV_) {
                    float y = trow[s] * sc + sh + acc[mt][nt][hh * 2 + 0];
                    orow[s] = fmaxf(y, 0.f);
                }
                if (s + 1 < TOV_) {
                    float y = trow[s + 1] * sc + sh + acc[mt][nt][hh * 2 + 1];
                    orow[s + 1] = fmaxf(y, 0.f);
                }
            }
        }
    }
}

// ---------------------------------------------------------------------------
extern "C" void kernel_launch(void* const* d_in, const int* in_sizes, int n_in,
                              void* d_out, int out_size) {
    const float* x       = (const float*)d_in[0];
    const float* A_parts = (const float*)d_in[1];
    const float* ei      = (const float*)d_in[2];
    const float* gcn_w   = (const float*)d_in[3];
    const float* gcn_b   = (const float*)d_in[4];
    const float* tcn_w   = (const float*)d_in[5];
    const float* tcn_b   = (const float*)d_in[6];
    const float* bn_g    = (const float*)d_in[7];
    const float* bn_b    = (const float*)d_in[8];
    const float* res_w   = (const float*)d_in[9];
    const float* res_b   = (const float*)d_in[10];
    float* out = (float*)d_out;

    cudaFuncSetAttribute(k_tcn_mma, cudaFuncAttributeMaxDynamicSharedMemorySize,
                         SMEM_TOT);
    cudaFuncSetAttribute(k_fin_mma, cudaFuncAttributeMaxDynamicSharedMemorySize,
                         SMEM_FIN);

    k_wprep<<<576, 128>>>(tcn_w, gcn_w);                 // 1
    k_beff<<<O_, 128>>>(tcn_w, gcn_b, tcn_b, res_w);     // 2
    dim3 gagg(ROWS_, N_);
    k_aggp<<<gagg, 256>>>(x, A_parts, ei);               // 3
    dim3 gtcn(5, 7, N_);
    k_tcn_mma<<<gtcn, 256, SMEM_TOT>>>();                // 4  <- profiled
    k_statsfin<<<1, 128>>>(bn_g, bn_b, res_b);           // 5
    dim3 gfin((TOV_ + 127) / 128, N_);
    k_fin_mma<<<gfin, 256, SMEM_FIN>>>(x, out);          // 6
}

// round 17
// speedup vs baseline: 1.2348x; 1.0207x over previous
#include <cuda_runtime.h>
#include <cuda_fp16.h>
#include <cstdint>

// Problem constants
#define N_   32
#define C_   64
#define T_   300
#define V_   25
#define O_   128
#define TO_  150
#define TV_  7500
#define TOV_ 3750
#define KT_  9
#define VP_  26                       // padded v stride for fp16 xtcn (even)

// Phase-split transposed agg layout: [n][v][row][c], row<224: even phase
// (t_in = 2*(row-2)), row>=224: odd phase (t_in = 2*(row-224-2)+1).
#define ROWS_ 448

__device__ __align__(4) __half g_xtcnH[(size_t)N_ * O_ * TO_ * VP_];  // 31.9 MB
__device__ float g_beff[O_ * TO_];
__device__ __align__(16) unsigned short g_aggB[(size_t)N_ * V_ * ROWS_ * 64];  // fp16
__device__ __align__(16) unsigned short g_WtapH[9 * 128 * 64];  // fp16 (single term)
__device__ __align__(16) unsigned short g_WresH[128 * 64];      // res_w hi
__device__ __align__(16) unsigned short g_WresL[128 * 64];      // res_w lo
__device__ double g_sum[O_];
__device__ double g_sum2[O_];

// ---------------- PTX helpers ------------------------------------------------
__device__ __forceinline__ uint32_t smem_u32(const void* p) {
    uint32_t a;
    asm("{ .reg .u64 t; cvta.to.shared.u64 t, %1; cvt.u32.u64 %0, t; }" : "=r"(a) : "l"(p));
    return a;
}
__device__ __forceinline__ void ldsm_x4(uint32_t* r, uint32_t addr) {
    asm volatile("ldmatrix.sync.aligned.m8n8.x4.shared.b16 {%0,%1,%2,%3}, [%4];"
                 : "=r"(r[0]), "=r"(r[1]), "=r"(r[2]), "=r"(r[3]) : "r"(addr));
}
__device__ __forceinline__ void mma_f16(float* d, const uint32_t* a, const uint32_t* b) {
    asm volatile(
        "mma.sync.aligned.m16n8k16.row.col.f32.f16.f16.f32 "
        "{%0,%1,%2,%3}, {%4,%5,%6,%7}, {%8,%9}, {%0,%1,%2,%3};"
        : "+f"(d[0]), "+f"(d[1]), "+f"(d[2]), "+f"(d[3])
        : "r"(a[0]), "r"(a[1]), "r"(a[2]), "r"(a[3]), "r"(b[0]), "r"(b[1]));
}
__device__ __forceinline__ void cp_async16(uint32_t dst, const void* src) {
    asm volatile("cp.async.cg.shared.global [%0], [%1], 16;" :: "r"(dst), "l"(src));
}
#define CP_COMMIT() asm volatile("cp.async.commit_group;" ::: "memory")
#define CP_WAIT0()  asm volatile("cp.async.wait_group 0;" ::: "memory")
#define SWZ128(x) ((x) ^ (((x) >> 3) & 0x70))

// ---------------------------------------------------------------------------
// L1: k_wprep — fused gcn*tcn weight -> swizzled fp16 per-tap images.
// ---------------------------------------------------------------------------
__global__ void __launch_bounds__(128) k_wprep(const float* __restrict__ tcn_w,
                                               const float* __restrict__ gcn_w) {
    __shared__ float gc[O_];
    int ck = blockIdx.x;
    int c = ck / KT_, k = ck % KT_;
    int o = threadIdx.x;
    gc[o] = gcn_w[o * C_ + c];
    __syncthreads();
    const float* wrow = tcn_w + (size_t)o * O_ * KT_ + k;
    float s = 0.f;
    #pragma unroll 8
    for (int o2 = 0; o2 < O_; o2++) s += wrow[o2 * KT_] * gc[o2];
    __half h = __float2half_rn(s);
    uint32_t boff = SWZ128((uint32_t)(o * 128 + c * 2));
    g_WtapH[k * 8192 + (boff >> 1)] = *reinterpret_cast<unsigned short*>(&h);
}

// ---------------------------------------------------------------------------
// L2: k_beff — bias_eff + zero stats accumulators + res_w hi/lo images
// ---------------------------------------------------------------------------
__global__ void __launch_bounds__(128) k_beff(const float* __restrict__ tcn_w,
                                              const float* __restrict__ gcn_b,
                                              const float* __restrict__ tcn_b,
                                              const float* __restrict__ res_w) {
    __shared__ float red[128];
    __shared__ float Bk[KT_];
    int o = blockIdx.x, o2 = threadIdx.x;
    if (o2 == 0) { g_sum[o] = 0.0; g_sum2[o] = 0.0; }
    if (o2 < 64) {
        float w = res_w[o * C_ + o2];
        __half h = __float2half_rn(w);
        __half l = __float2half_rn(w - __half2float(h));
        uint32_t boff = SWZ128((uint32_t)(o * 128 + o2 * 2));
        g_WresH[boff >> 1] = *reinterpret_cast<unsigned short*>(&h);
        g_WresL[boff >> 1] = *reinterpret_cast<unsigned short*>(&l);
    }
    float gb = gcn_b[o2];
    const float* wrow = tcn_w + ((size_t)o * O_ + o2) * KT_;
    #pragma unroll
    for (int k = 0; k < KT_; k++) {
        red[o2] = wrow[k] * gb;
        __syncthreads();
        for (int st = 64; st > 0; st >>= 1) {
            if (o2 < st) red[o2] += red[o2 + st];
            __syncthreads();
        }
        if (o2 == 0) Bk[k] = red[0];
        __syncthreads();
    }
    float tb = tcn_b[o];
    for (int t = threadIdx.x; t < TO_; t += 128) {
        float s = tb;
        #pragma unroll
        for (int k = 0; k < KT_; k++) {
            int tp = 2 * t + k - 4;
            if (tp >= 0 && tp < T_) s += Bk[k];
        }
        g_beff[o * TO_ + t] = s;
    }
}

// ---------------------------------------------------------------------------
// L3: k_aggp — agg in phase-split transposed fp16 layout.
// LDS-optimized: v-quad per thread (1 sx LDS + 1 broadcast float4 per 4 FMA).
// ---------------------------------------------------------------------------
__global__ void __launch_bounds__(256) k_aggp(const float* __restrict__ x,
                                              const float* __restrict__ A_parts,
                                              const float* __restrict__ ei) {
    __shared__ float sx[64 * 27];                 // [c][w] pitch 27
    __shared__ float As4[25 * 28];                // [w][v] pitch 28 (padded)
    __shared__ __align__(16) unsigned short souts[1600];
    int row = blockIdx.x, n = blockIdx.y, tid = threadIdx.x;
    int phase = (row >= 224) ? 1 : 0;
    int e = phase ? (row - 224) : row;
    int t_in = 2 * (e - 2) + phase;
    bool valid = (t_in >= 0) && (t_in < T_);

    if (valid) {
        float e0 = ei[0], e1 = ei[1], e2 = ei[2];
        for (int i = tid; i < 700; i += 256) {
            int w = i / 28, v = i - w * 28;
            float val = 0.f;
            if (v < 25) {
                int idx = w * 25 + v;
                val = A_parts[idx] * e0 + A_parts[625 + idx] * e1 +
                      A_parts[1250 + idx] * e2;
            }
            As4[i] = val;
        }
        const float* xb = x + ((size_t)n * C_) * TV_ + t_in * V_;
        for (int i = tid; i < 1600; i += 256) {
            int c = i / 25, w = i - c * 25;
            sx[c * 27 + w] = xb[c * TV_ + w];
        }
        __syncthreads();
        // tasks: 64 c x 7 vq = 448
        for (int task = tid; task < 448; task += 256) {
            int c = task & 63, vq = task >> 6;
            float a0 = 0.f, a1 = 0.f, a2 = 0.f, a3 = 0.f;
            const float* sxr = sx + c * 27;
            #pragma unroll
            for (int w = 0; w < 25; w++) {
                float xv = sxr[w];
                float4 a = *(const float4*)&As4[w * 28 + vq * 4];
                a0 += xv * a.x; a1 += xv * a.y; a2 += xv * a.z; a3 += xv * a.w;
            }
            int v0 = vq * 4;
            float accv[4] = {a0, a1, a2, a3};
            #pragma unroll
            for (int j = 0; j < 4; j++) {
                int v = v0 + j;
                if (v < 25) {
                    __half h = __float2half_rn(accv[j]);
                    souts[v * 64 + c] = *reinterpret_cast<unsigned short*>(&h);
                }
            }
        }
        __syncthreads();
        int r7 = row & 7;
        for (int j = tid; j < 200; j += 256) {
            int v = j >> 3, q = j & 7;
            uint4 val = *(const uint4*)&souts[v * 64 + ((q ^ r7) << 3)];
            *((uint4*)(g_aggB + (((size_t)(n * 25 + v) * ROWS_ + row) << 6)) + q) = val;
        }
    } else {
        for (int j = tid; j < 200; j += 256) {
            int v = j >> 3, q = j & 7;
            *((uint4*)(g_aggB + (((size_t)(n * 25 + v) * ROWS_ + row) << 6)) + q) =
                make_uint4(0, 0, 0, 0);
        }
    }
}

// ---------------------------------------------------------------------------
// L4 (profiled slot): k_tcn_mma — tap-shift HMMA fp16 single-term,
// double-buffered A via cp.async, 4 consecutive v per CTA, STAGED epilogue,
// fp16 output (padded v stride 26).
// CTA tile: 128 o x (4 v x 32 t).  Warp: 64 o x (1 v x 32 t).
// ---------------------------------------------------------------------------
#define BROWS  40
#define BSEC   (BROWS * 128)          // 5120
#define TB_OFF 0
#define TA0    40960
#define TA1    57344
#define SMEM_TOT 73728

__global__ void __launch_bounds__(256, 2) k_tcn_mma() {
    extern __shared__ __align__(16) unsigned char smem[];
    int tid = threadIdx.x, lane = tid & 31, wid = tid >> 5;
    int wm = wid >> 2;                 // 0..1 (o half)
    int vsec_w = wid & 3;              // 0..3 (one v per warp)
    int t0 = blockIdx.x * 32;
    int v0 = blockIdx.y * 4;
    int n = blockIdx.z;
    uint32_t sbase = smem_u32(smem);

    // ---- B copy: 8 sections (vsec 0..3, phase 0..1) x 36 rows used
    for (int j = tid; j < 2304; j += 256) {
        int sec = j / 288;
        int rq = j - sec * 288;
        int row = rq >> 3, q = rq & 7;   // row 0..35
        int vsec = sec >> 1, phase = sec & 1;
        int vv = v0 + vsec;
        uint4 val = make_uint4(0, 0, 0, 0);
        if (vv < V_) {
            int grow = (phase ? 224 : 0) + t0 + row;
            val = *((const uint4*)(g_aggB +
                    (((size_t)(n * V_ + vv) * ROWS_ + grow) << 6)) + q);
        }
        *((uint4*)(smem + TB_OFF + sec * BSEC + row * 128) + q) = val;
    }

    // ---- prologue: A tap 0 -> buf0 via cp.async (16KB = 1024 x 16B)
    {
        #pragma unroll
        for (int i = 0; i < 4; i++) {
            int idx = tid + 256 * i;
            cp_async16(sbase + TA0 + idx * 16, (const void*)(g_WtapH + idx * 8));
        }
        CP_COMMIT();
    }

    // fragment addressing
    int la_row = ((lane >> 3) & 1) * 8 + (lane & 7);
    uint32_t xorA = (uint32_t)((lane & 7) << 4);
    uint32_t la_col = ((lane >> 4) & 1) * 16;
    uint32_t aRow = (uint32_t)(wm * 64 + la_row) * 128;
    uint32_t lb_col = (uint32_t)(((lane >> 3) & 1) * 16);
    uint32_t lrow8 = (uint32_t)(((lane >> 4) & 1) * 8 + (lane & 7));

    float acc[4][4][4] = {};

    CP_WAIT0();
    __syncthreads();

    for (int k = 0; k < 9; k++) {
        uint32_t abuf = (k & 1) ? TA1 : TA0;
        if (k < 8) {
            uint32_t nbuf = (k & 1) ? TA0 : TA1;
            const unsigned short* srcH = g_WtapH + (k + 1) * 8192;
            #pragma unroll
            for (int i = 0; i < 4; i++) {
                int idx = tid + 256 * i;
                cp_async16(sbase + nbuf + idx * 16, (const void*)(srcH + idx * 8));
            }
            CP_COMMIT();
        }

        int phase = k & 1, jt = k >> 1;
        uint32_t secoff = (uint32_t)(vsec_w * 2 + phase) * BSEC;
        uint32_t xorB = (uint32_t)(((jt + (lane & 7)) & 7) << 4);
        uint32_t rb4 = (uint32_t)jt + lrow8;

        #pragma unroll
        for (int ks = 0; ks < 4; ks++) {
            uint32_t cb = ((uint32_t)(ks * 32) + lb_col) ^ xorB;
            uint32_t bh[4][2];
            {
                uint32_t a0 = sbase + TB_OFF + secoff + rb4 * 128 + cb;
                ldsm_x4(&bh[0][0], a0);
                ldsm_x4(&bh[2][0], a0 + 16 * 128);
            }
            uint32_t ca = ((uint32_t)(ks * 32) + la_col) ^ xorA;
            #pragma unroll
            for (int mt = 0; mt < 4; mt++) {
                uint32_t ah[4];
                ldsm_x4(ah, abuf + sbase + aRow + mt * 2048 + ca);
                #pragma unroll
                for (int nt = 0; nt < 4; nt++)
                    mma_f16(acc[mt][nt], ah, bh[nt]);
            }
        }

        if (k < 8) CP_WAIT0();
        __syncthreads();
    }

    // ---- staged epilogue + fused stats (smem fully reusable now)
    float* stage = (float*)smem;                    // 128 x 132 (padded)
    float* ssum  = (float*)(smem + 128 * 132 * 4);  // 67584
    float* ssum2 = ssum + 128;                      // ends 68608 <= 73728
    if (tid < 128) { ssum[tid] = 0.f; ssum2[tid] = 0.f; }
    __syncthreads();

    int qr = lane >> 2, qc = (lane & 3) * 2;
    int vv = v0 + vsec_w;
    bool vok = vv < V_;
    #pragma unroll
    for (int mt = 0; mt < 4; mt++) {
        #pragma unroll
        for (int hh = 0; hh < 2; hh++) {
            int o = wm * 64 + mt * 16 + qr + hh * 8;
            const float* be = g_beff + o * TO_;
            float s1 = 0.f, s2 = 0.f;
            #pragma unroll
            for (int nt = 0; nt < 4; nt++) {
                int tloc = nt * 8 + qc;
                int t = t0 + tloc;
                float y0 = 0.f, y1 = 0.f;
                if (vok && t < TO_) {
                    y0 = acc[mt][nt][hh * 2 + 0] + be[t];
                    s1 += y0; s2 += y0 * y0;
                }
                if (vok && t + 1 < TO_) {
                    y1 = acc[mt][nt][hh * 2 + 1] + be[t + 1];
                    s1 += y1; s2 += y1 * y1;
                }
                stage[o * 132 + tloc * 4 + vsec_w] = y0;
                stage[o * 132 + (tloc + 1) * 4 + vsec_w] = y1;
            }
            s1 += __shfl_xor_sync(0xFFFFFFFFu, s1, 1);
            s1 += __shfl_xor_sync(0xFFFFFFFFu, s1, 2);
            s2 += __shfl_xor_sync(0xFFFFFFFFu, s2, 1);
            s2 += __shfl_xor_sync(0xFFFFFFFFu, s2, 2);
            if ((lane & 3) == 0) {
                atomicAdd(&ssum[o], s1);
                atomicAdd(&ssum2[o], s2);
            }
        }
    }
    __syncthreads();

    // copy-out: half2 pairs (v pairs), padded stride VP_=26 (even -> aligned)
    for (int j = tid; j < 8192; j += 256) {
        int o = j >> 6, r = j & 63;
        int tl = r >> 1, vp = r & 1;     // v pair index 0/1 -> v offsets 0,2
        int t = t0 + tl;
        int vv2 = v0 + vp * 2;
        if (t < TO_ && vv2 < VP_ && vv2 < V_ + 1) {
            float y0 = stage[o * 132 + tl * 4 + vp * 2];
            float y1 = stage[o * 132 + tl * 4 + vp * 2 + 1];
            __half2 h2 = __floats2half2_rn(y0, y1);
            *reinterpret_cast<__half2*>(
                g_xtcnH + (((size_t)n * O_ + o) * TO_ + t) * VP_ + vv2) = h2;
        }
    }
    if (tid < 128) {
        atomicAdd(&g_sum[tid], (double)ssum[tid]);
        atomicAdd(&g_sum2[tid], (double)ssum2[tid]);
    }
}

// ---------------------------------------------------------------------------
// L5: k_fin_mma — residual HMMA (K=64, res_w 2-term) + BN + add + ReLU.
// statsfin folded in (per-CTA scale/shift compute). Coalesced s-epilogue.
// smem: B 16KB | A hi 16KB | A lo 16KB | sc/sh 1KB
// ---------------------------------------------------------------------------
#define FB_OFF 0
#define FAH    16384
#define FAL    32768
#define FSC    49152
#define SMEM_FIN 50176

__global__ void __launch_bounds__(256, 2) k_fin_mma(const float* __restrict__ x,
                                                    const float* __restrict__ gamma,
                                                    const float* __restrict__ beta,
                                                    const float* __restrict__ res_b,
                                                    float* __restrict__ out) {
    extern __shared__ __align__(16) unsigned char smem[];
    int tid = threadIdx.x, lane = tid & 31, wid = tid >> 5;
    int wm = wid >> 2, wn = wid & 3;
    int n = blockIdx.y;
    int s0 = blockIdx.x * 128;
    uint32_t sbase = smem_u32(smem);
    float* s_sc = (float*)(smem + FSC);
    float* s_sh = s_sc + 128;

    // scale/shift (statsfin folded): threads 0..127
    if (tid < 128) {
        double cnt = (double)N_ * (double)TOV_;
        double mean = g_sum[tid] / cnt;
        double var = g_sum2[tid] / cnt - mean * mean;
        float rstd = (float)(1.0 / sqrt(var + 1e-5));
        float sc = gamma[tid] * rstd;
        s_sc[tid] = sc;
        s_sh[tid] = beta[tid] - (float)mean * sc + res_b[tid];
    }

    // A copy (res_w hi/lo images, 16KB each = 1024 uint4 each)
    #pragma unroll
    for (int i = 0; i < 8; i++) {
        int j = tid + 256 * i;                // 0..2047
        int p = j >> 10, idx = j & 1023;
        *((uint4*)(smem + (p ? FAL : FAH)) + idx) =
            *((const uint4*)(p ? g_WresL : g_WresH) + idx);
    }

    // B gather: thread covers s-row r, 32 c values (half selects c range)
    {
        int r = tid & 127, half = tid >> 7;
        int s = s0 + r;
        bool valid = s < TOV_;
        int t2 = valid ? (s / V_) * 2 : 0;
        int v = valid ? (s % V_) : 0;
        const float* xb = x + (size_t)n * C_ * TV_ + (size_t)t2 * V_ + v;
        int xors = (r & 7) << 4;
        #pragma unroll
        for (int j = 0; j < 16; j++) {
            int c0 = half * 32 + j * 2;
            float f0 = valid ? xb[(size_t)c0 * TV_] : 0.f;
            float f1 = valid ? xb[(size_t)(c0 + 1) * TV_] : 0.f;
            __half h0 = __float2half_rn(f0);
            __half h1 = __float2half_rn(f1);
            uint32_t pair = (uint32_t)*reinterpret_cast<unsigned short*>(&h0) |
                            ((uint32_t)*reinterpret_cast<unsigned short*>(&h1) << 16);
            uint32_t off = (uint32_t)(r * 128 + ((c0 * 2) ^ xors));
            *reinterpret_cast<uint32_t*>(smem + FB_OFF + off) = pair;
        }
    }
    __syncthreads();

    // fragment addressing
    int la_row = ((lane >> 3) & 1) * 8 + (lane & 7);
    uint32_t xorA = (uint32_t)((lane & 7) << 4);
    uint32_t la_col = ((lane >> 4) & 1) * 16;
    uint32_t aRow = (uint32_t)(wm * 64 + la_row) * 128;
    uint32_t lb_col = (uint32_t)(((lane >> 3) & 1) * 16);
    uint32_t lrow8 = (uint32_t)(((lane >> 4) & 1) * 8 + (lane & 7));
    uint32_t rb4 = (uint32_t)(wn * 32) + lrow8;
    uint32_t xorB = (uint32_t)((lane & 7) << 4);

    float acc[4][4][4] = {};

    #pragma unroll
    for (int ks = 0; ks < 4; ks++) {
        uint32_t cb = ((uint32_t)(ks * 32) + lb_col) ^ xorB;
        uint32_t bh[4][2];
        {
            uint32_t a0 = sbase + FB_OFF + rb4 * 128 + cb;
            ldsm_x4(&bh[0][0], a0);
            ldsm_x4(&bh[2][0], a0 + 16 * 128);
        }
        uint32_t ca = ((uint32_t)(ks * 32) + la_col) ^ xorA;
        #pragma unroll
        for (int mt = 0; mt < 4; mt++) {
            uint32_t ah[4], al[4];
            ldsm_x4(ah, sbase + FAH + aRow + mt * 2048 + ca);
            ldsm_x4(al, sbase + FAL + aRow + mt * 2048 + ca);
            #pragma unroll
            for (int nt = 0; nt < 4; nt++) {
                mma_f16(acc[mt][nt], ah, bh[nt]);
                mma_f16(acc[mt][nt], al, bh[nt]);
            }
        }
    }

    // epilogue: out = relu(xtcn*scale + shift + res)   (res_b in shift)
    const __half* Tcn = g_xtcnH + (size_t)n * O_ * TO_ * VP_;
    float* Out = out + (size_t)n * O_ * TOV_;
    int qr = lane >> 2, qc = (lane & 3) * 2;
    #pragma unroll
    for (int mt = 0; mt < 4; mt++) {
        #pragma unroll
        for (int hh = 0; hh < 2; hh++) {
            int o = wm * 64 + mt * 16 + qr + hh * 8;
            float sc = s_sc[o];
            float sh = s_sh[o];
            const __half* trow = Tcn + (size_t)o * TO_ * VP_;
            float* orow = Out + (size_t)o * TOV_;
            #pragma unroll
            for (int nt = 0; nt < 4; nt++) {
                int s = s0 + wn * 32 + nt * 8 + qc;
                if (s < TOV_) {
                    int t = s / V_, v = s - t * V_;
                    float y = __half2float(trow[t * VP_ + v]) * sc + sh +
                              acc[mt][nt][hh * 2 + 0];
                    orow[s] = fmaxf(y, 0.f);
                }
                if (s + 1 < TOV_) {
                    int t = (s + 1) / V_, v = (s + 1) - t * V_;
                    float y = __half2float(trow[t * VP_ + v]) * sc + sh +
                              acc[mt][nt][hh * 2 + 1];
                    orow[s + 1] = fmaxf(y, 0.f);
                }
            }
        }
    }
}

// ---------------------------------------------------------------------------
extern "C" void kernel_launch(void* const* d_in, const int* in_sizes, int n_in,
                              void* d_out, int out_size) {
    const float* x       = (const float*)d_in[0];
    const float* A_parts = (const float*)d_in[1];
    const float* ei      = (const float*)d_in[2];
    const float* gcn_w   = (const float*)d_in[3];
    const float* gcn_b   = (const float*)d_in[4];
    const float* tcn_w   = (const float*)d_in[5];
    const float* tcn_b   = (const float*)d_in[6];
    const float* bn_g    = (const float*)d_in[7];
    const float* bn_b    = (const float*)d_in[8];
    const float* res_w   = (const float*)d_in[9];
    const float* res_b   = (const float*)d_in[10];
    float* out = (float*)d_out;

    cudaFuncSetAttribute(k_tcn_mma, cudaFuncAttributeMaxDynamicSharedMemorySize,
                         SMEM_TOT);
    cudaFuncSetAttribute(k_fin_mma, cudaFuncAttributeMaxDynamicSharedMemorySize,
                         SMEM_FIN);

    k_wprep<<<576, 128>>>(tcn_w, gcn_w);                 // 1
    k_beff<<<O_, 128>>>(tcn_w, gcn_b, tcn_b, res_w);     // 2
    dim3 gagg(ROWS_, N_);
    k_aggp<<<gagg, 256>>>(x, A_parts, ei);               // 3
    dim3 gtcn(5, 7, N_);
    k_tcn_mma<<<gtcn, 256, SMEM_TOT>>>();                // 4  <- profiled
    dim3 gfin((TOV_ + 127) / 128, N_);
    k_fin_mma<<<gfin, 256, SMEM_FIN>>>(x, bn_g, bn_b, res_b, out);  // 5
}